// round 1
// baseline (speedup 1.0000x reference)
#include <cuda_runtime.h>
#include <cstdint>
#include <cstdio>

#define T_TOK 4096
#define H_DIM 1024
#define I_DIM 1024
#define E_NUM 8
#define S_SLOTS (T_TOK * 2)          // 8192 token-expert slots
#define BM 128
#define BK 8
#define MAX_TILES (S_SLOTS / BM + E_NUM)   // 72: worst-case row tiles

// ---------------- scratch (device globals: allocation-free rule) ----------------
__device__ int   d_counts[E_NUM];
__device__ int   d_expert_of_slot[S_SLOTS];
__device__ float d_w_of_slot[S_SLOTS];
__device__ int   d_perm[S_SLOTS];              // perm[pos] = slot id
__device__ int   d_tile_expert[MAX_TILES];
__device__ int   d_tile_row0[MAX_TILES];
__device__ int   d_tile_rowend[MAX_TILES];
__device__ int   d_num_tiles;
__device__ __align__(16) float d_hbuf[(size_t)S_SLOTS * I_DIM];  // 32 MB
__device__ __align__(16) float d_acc [(size_t)S_SLOTS * H_DIM];  // 32 MB

// ---------------- packed fp32x2 FMA (B300 FFMA2 path) ----------------
__device__ __forceinline__ void ffma2(float2& d, const float2& a, const float2& b) {
    asm("fma.rn.f32x2 %0, %1, %2, %0;"
        : "+l"(reinterpret_cast<unsigned long long&>(d))
        : "l"(reinterpret_cast<const unsigned long long&>(a)),
          "l"(reinterpret_cast<const unsigned long long&>(b)));
}
__device__ __forceinline__ float2 bcast2(float x) {
    float2 r;
    asm("mov.b64 %0, {%1, %1};"
        : "=l"(reinterpret_cast<unsigned long long&>(r)) : "f"(x));
    return r;
}

// ---------------- kernel 0: zero expert counts ----------------
__global__ void zero_counts_kernel() {
    if (threadIdx.x < E_NUM) d_counts[threadIdx.x] = 0;
}

// ---------------- kernel 1: router (softmax+top2+renorm collapses to sigmoid) --
__global__ void router_kernel(const float* __restrict__ logits) {
    int t = blockIdx.x * blockDim.x + threadIdx.x;
    if (t >= T_TOK) return;
    float l[E_NUM];
#pragma unroll
    for (int e = 0; e < E_NUM; e++) l[e] = logits[t * E_NUM + e];
    int i0 = 0;
#pragma unroll
    for (int e = 1; e < E_NUM; e++) if (l[e] > l[i0]) i0 = e;
    int i1 = (i0 == 0) ? 1 : 0;
#pragma unroll
    for (int e = 0; e < E_NUM; e++) {
        if (e == i0 || e == i1) continue;
        if (l[e] > l[i1]) i1 = e;
    }
    // renormalized top-2 softmax weights: softmax denom cancels exactly
    float w0 = 1.f / (1.f + expf(l[i1] - l[i0]));
    d_expert_of_slot[2 * t]     = i0;
    d_expert_of_slot[2 * t + 1] = i1;
    d_w_of_slot[2 * t]     = w0;
    d_w_of_slot[2 * t + 1] = 1.f - w0;
    atomicAdd(&d_counts[i0], 1);
    atomicAdd(&d_counts[i1], 1);
}

// ---------------- kernel 2: offsets + tile map + scatter (counting sort) -------
__global__ void setup_kernel() {
    __shared__ int s_off[E_NUM];
    __shared__ int s_cur[E_NUM];
    if (threadIdx.x == 0) {
        int acc = 0, nt = 0;
        for (int e = 0; e < E_NUM; e++) {
            int c = d_counts[e];
            s_off[e] = acc;
            for (int r = 0; r < c; r += BM) {
                d_tile_expert[nt] = e;
                d_tile_row0[nt]   = acc + r;
                d_tile_rowend[nt] = acc + c;
                nt++;
            }
            acc += c;
        }
        d_num_tiles = nt;
    }
    if (threadIdx.x < E_NUM) s_cur[threadIdx.x] = 0;
    __syncthreads();
    for (int s = threadIdx.x; s < S_SLOTS; s += blockDim.x) {
        int e = d_expert_of_slot[s];
        int pos = s_off[e] + atomicAdd(&s_cur[e], 1);
        d_perm[pos] = s;
    }
}

// ---------------- kernel 3: grouped GEMM1 (gate+up) + fused SiLU ---------------
// grid: (16 column-blocks of 64, MAX_TILES row tiles); block: 256 threads
// each block: rows [row0,row0+128) x {gate cols [nb*64,+64), up cols I+same}
__global__ __launch_bounds__(256, 2)
void gemm1_kernel(const float* __restrict__ x, const float* __restrict__ up_w) {
    int tile = blockIdx.y;
    if (tile >= d_num_tiles) return;
    const int e      = d_tile_expert[tile];
    const int row0   = d_tile_row0[tile];
    const int rowend = d_tile_rowend[tile];
    const int nb     = blockIdx.x;

    __shared__ float As[BK][BM + 4];   // transposed, padded (bank-conflict-free)
    __shared__ float Bg[BK][64];
    __shared__ float Bu[BK][64];

    const int tid = threadIdx.x;
    const int tx = tid & 15;    // column group (cols tx*2, tx*2+1, +32, +33)
    const int ty = tid >> 4;    // row group (rows ty*8 .. ty*8+7)

    // A gather mapping: 2 threads per row, one float4 each
    const int ar = tid >> 1;
    const int ak = (tid & 1) * 4;
    const int grow = row0 + ar;
    const float* arow = nullptr;
    if (grow < rowend) {
        int token = d_perm[grow] >> 1;   // slot -> token
        arow = x + (size_t)token * H_DIM;
    }

    // B mapping: 128 threads gate half, 128 threads up half; one float4 each
    const int half = tid >> 7;
    const int btid = tid & 127;
    const int bk = btid >> 4;
    const int bn = (btid & 15) * 4;
    const float* Bsrc = up_w + (size_t)e * H_DIM * (2 * I_DIM)
                      + (half ? (I_DIM + nb * 64) : (nb * 64)) + bn;

    float2 accg[8][2], accu[8][2];
#pragma unroll
    for (int i = 0; i < 8; i++)
#pragma unroll
        for (int j = 0; j < 2; j++) {
            accg[i][j] = make_float2(0.f, 0.f);
            accu[i][j] = make_float2(0.f, 0.f);
        }

    for (int k0 = 0; k0 < H_DIM; k0 += BK) {
        float4 av = make_float4(0.f, 0.f, 0.f, 0.f);
        if (arow) av = *(const float4*)(arow + k0 + ak);
        As[ak + 0][ar] = av.x; As[ak + 1][ar] = av.y;
        As[ak + 2][ar] = av.z; As[ak + 3][ar] = av.w;
        float4 bv = *(const float4*)(Bsrc + (size_t)(k0 + bk) * (2 * I_DIM));
        *(float4*)(half ? &Bu[bk][bn] : &Bg[bk][bn]) = bv;
        __syncthreads();
#pragma unroll
        for (int kk = 0; kk < BK; kk++) {
            float4 a03 = *(const float4*)&As[kk][ty * 8];
            float4 a47 = *(const float4*)&As[kk][ty * 8 + 4];
            float2 bg0 = *(const float2*)&Bg[kk][tx * 2];
            float2 bg1 = *(const float2*)&Bg[kk][tx * 2 + 32];
            float2 bu0 = *(const float2*)&Bu[kk][tx * 2];
            float2 bu1 = *(const float2*)&Bu[kk][tx * 2 + 32];
            float a[8] = {a03.x, a03.y, a03.z, a03.w, a47.x, a47.y, a47.z, a47.w};
#pragma unroll
            for (int i = 0; i < 8; i++) {
                float2 aa = bcast2(a[i]);
                ffma2(accg[i][0], aa, bg0);
                ffma2(accg[i][1], aa, bg1);
                ffma2(accu[i][0], aa, bu0);
                ffma2(accu[i][1], aa, bu1);
            }
        }
        __syncthreads();
    }

    // epilogue: h = silu(gate) * up -> hbuf (compact row layout)
#pragma unroll
    for (int i = 0; i < 8; i++) {
        int r = row0 + ty * 8 + i;
        if (r >= rowend) continue;
        float2 h0, h1;
        {
            float g = accg[i][0].x, u = accu[i][0].x;
            h0.x = (g / (1.f + expf(-g))) * u;
            g = accg[i][0].y; u = accu[i][0].y;
            h0.y = (g / (1.f + expf(-g))) * u;
            g = accg[i][1].x; u = accu[i][1].x;
            h1.x = (g / (1.f + expf(-g))) * u;
            g = accg[i][1].y; u = accu[i][1].y;
            h1.y = (g / (1.f + expf(-g))) * u;
        }
        float* dst = &d_hbuf[(size_t)r * I_DIM + nb * 64 + tx * 2];
        *(float2*)dst = h0;
        *(float2*)(dst + 32) = h1;
    }
}

// ---------------- kernel 4: grouped GEMM2 (down) + weight in epilogue ----------
// grid: (8 column blocks of 128, MAX_TILES); block 256 threads, 8x8 per thread
__global__ __launch_bounds__(256, 2)
void gemm2_kernel(const float* __restrict__ down_w) {
    int tile = blockIdx.y;
    if (tile >= d_num_tiles) return;
    const int e      = d_tile_expert[tile];
    const int row0   = d_tile_row0[tile];
    const int rowend = d_tile_rowend[tile];
    const int n0     = blockIdx.x * 128;

    __shared__ float As[BK][BM + 4];
    __shared__ float Bs[BK][128];

    const int tid = threadIdx.x;
    const int tx = tid & 15;   // cols tx*2 + 32*j, j=0..3
    const int ty = tid >> 4;   // rows ty*8 .. +7

    const int ar = tid >> 1;
    const int ak = (tid & 1) * 4;
    const int grow = row0 + ar;
    const bool avalid = (grow < rowend);

    const int bk = tid >> 5;
    const int bn = (tid & 31) * 4;
    const float* Bsrc = down_w + (size_t)e * I_DIM * H_DIM + n0 + bn;

    float2 acc[8][4];
#pragma unroll
    for (int i = 0; i < 8; i++)
#pragma unroll
        for (int j = 0; j < 4; j++) acc[i][j] = make_float2(0.f, 0.f);

    for (int k0 = 0; k0 < I_DIM; k0 += BK) {
        float4 av = make_float4(0.f, 0.f, 0.f, 0.f);
        if (avalid) av = *(const float4*)&d_hbuf[(size_t)grow * I_DIM + k0 + ak];
        As[ak + 0][ar] = av.x; As[ak + 1][ar] = av.y;
        As[ak + 2][ar] = av.z; As[ak + 3][ar] = av.w;
        *(float4*)&Bs[bk][bn] = *(const float4*)(Bsrc + (size_t)(k0 + bk) * H_DIM);
        __syncthreads();
#pragma unroll
        for (int kk = 0; kk < BK; kk++) {
            float4 a03 = *(const float4*)&As[kk][ty * 8];
            float4 a47 = *(const float4*)&As[kk][ty * 8 + 4];
            float2 b0 = *(const float2*)&Bs[kk][tx * 2];
            float2 b1 = *(const float2*)&Bs[kk][tx * 2 + 32];
            float2 b2 = *(const float2*)&Bs[kk][tx * 2 + 64];
            float2 b3 = *(const float2*)&Bs[kk][tx * 2 + 96];
            float a[8] = {a03.x, a03.y, a03.z, a03.w, a47.x, a47.y, a47.z, a47.w};
#pragma unroll
            for (int i = 0; i < 8; i++) {
                float2 aa = bcast2(a[i]);
                ffma2(acc[i][0], aa, b0);
                ffma2(acc[i][1], aa, b1);
                ffma2(acc[i][2], aa, b2);
                ffma2(acc[i][3], aa, b3);
            }
        }
        __syncthreads();
    }

#pragma unroll
    for (int i = 0; i < 8; i++) {
        int r = row0 + ty * 8 + i;
        if (r >= rowend) continue;
        int slot = d_perm[r];
        float w = d_w_of_slot[slot];
        float* dst = &d_acc[(size_t)slot * H_DIM + n0 + tx * 2];
#pragma unroll
        for (int j = 0; j < 4; j++) {
            float2 v = make_float2(w * acc[i][j].x, w * acc[i][j].y);
            *(float2*)(dst + 32 * j) = v;
        }
    }
}

// ---------------- kernel 5: combine the two expert slots per token -------------
__global__ void combine_kernel(float* __restrict__ out) {
    int i = blockIdx.x * blockDim.x + threadIdx.x;
    if (i >= T_TOK * H_DIM / 4) return;
    int t = i / (H_DIM / 4);
    int c = i % (H_DIM / 4);
    const float4* a0 = (const float4*)&d_acc[(size_t)(2 * t) * H_DIM];
    const float4* a1 = (const float4*)&d_acc[(size_t)(2 * t + 1) * H_DIM];
    float4 x0 = a0[c], x1 = a1[c];
    ((float4*)out)[i] = make_float4(x0.x + x1.x, x0.y + x1.y,
                                    x0.z + x1.z, x0.w + x1.w);
}

// ---------------- launch ----------------
extern "C" void kernel_launch(void* const* d_in, const int* in_sizes, int n_in,
                              void* d_out, int out_size) {
    (void)in_sizes; (void)n_in; (void)out_size;
    const float* x      = (const float*)d_in[0];
    const float* logits = (const float*)d_in[1];
    const float* up_w   = (const float*)d_in[2];
    const float* down_w = (const float*)d_in[3];
    float* out = (float*)d_out;

    zero_counts_kernel<<<1, 32>>>();
    router_kernel<<<T_TOK / 256, 256>>>(logits);
    setup_kernel<<<1, 256>>>();
    gemm1_kernel<<<dim3(16, MAX_TILES), 256>>>(x, up_w);
    gemm2_kernel<<<dim3(8, MAX_TILES), 256>>>(down_w);
    combine_kernel<<<(T_TOK * H_DIM / 4 + 255) / 256, 256>>>(out);
}

// round 3
// speedup vs baseline: 1.3272x; 1.3272x over previous
#include <cuda_runtime.h>
#include <cuda_bf16.h>
#include <cstdint>

#define T_TOK 4096
#define H_DIM 1024
#define I_DIM 1024
#define E_NUM 8
#define S_SLOTS (T_TOK * 2)
#define BM 128
#define MAX_TILES (S_SLOTS / BM + E_NUM)   // 72

// ---------------- device scratch (allocation-free rule) ----------------
__device__ int   d_counts[E_NUM];
__device__ int   d_expert_of_slot[S_SLOTS];
__device__ float d_w_of_slot[S_SLOTS];
__device__ int   d_perm[S_SLOTS];
__device__ int   d_tile_expert[MAX_TILES];
__device__ int   d_tile_row0[MAX_TILES];
__device__ int   d_tile_rowend[MAX_TILES];
__device__ int   d_num_tiles;

__device__ __align__(16) __nv_bfloat16 d_x_h[(size_t)T_TOK * H_DIM];
__device__ __align__(16) __nv_bfloat16 d_x_l[(size_t)T_TOK * H_DIM];
__device__ __align__(16) __nv_bfloat16 d_upwT_h[(size_t)E_NUM * 2 * I_DIM * H_DIM]; // [e][n][k]
__device__ __align__(16) __nv_bfloat16 d_upwT_l[(size_t)E_NUM * 2 * I_DIM * H_DIM];
__device__ __align__(16) __nv_bfloat16 d_dnwT_h[(size_t)E_NUM * H_DIM * I_DIM];     // [e][n][k]
__device__ __align__(16) __nv_bfloat16 d_dnwT_l[(size_t)E_NUM * H_DIM * I_DIM];
__device__ __align__(16) __nv_bfloat16 d_hbuf_h[(size_t)S_SLOTS * I_DIM];
__device__ __align__(16) __nv_bfloat16 d_hbuf_l[(size_t)S_SLOTS * I_DIM];
__device__ __align__(16) float d_acc[(size_t)S_SLOTS * H_DIM];                      // 32 MB

// ---------------- PTX helpers ----------------
__device__ __forceinline__ uint32_t smem_u32(const void* p) {
    uint32_t a;
    asm("{ .reg .u64 t; cvta.to.shared.u64 t, %1; cvt.u32.u64 %0, t; }" : "=r"(a) : "l"(p));
    return a;
}
#define CP_ASYNC16(sm, gp, sz) \
    asm volatile("cp.async.cg.shared.global [%0], [%1], 16, %2;" :: "r"(sm), "l"(gp), "r"(sz) : "memory")
#define CP_COMMIT() asm volatile("cp.async.commit_group;" ::: "memory")
#define CP_WAIT1()  asm volatile("cp.async.wait_group 1;" ::: "memory")
#define CP_WAIT0()  asm volatile("cp.async.wait_group 0;" ::: "memory")
#define LDSM_X4(r0, r1, r2, r3, addr) \
    asm volatile("ldmatrix.sync.aligned.m8n8.x4.shared.b16 {%0,%1,%2,%3}, [%4];" \
        : "=r"(r0), "=r"(r1), "=r"(r2), "=r"(r3) : "r"(addr))

__device__ __forceinline__ void mma_bf16(float* d, const uint32_t* a, uint32_t b0, uint32_t b1) {
    asm volatile("mma.sync.aligned.m16n8k16.row.col.f32.bf16.bf16.f32 "
        "{%0,%1,%2,%3}, {%4,%5,%6,%7}, {%8,%9}, {%0,%1,%2,%3};"
        : "+f"(d[0]), "+f"(d[1]), "+f"(d[2]), "+f"(d[3])
        : "r"(a[0]), "r"(a[1]), "r"(a[2]), "r"(a[3]), "r"(b0), "r"(b1));
}

__device__ __forceinline__ uint32_t packbf(float a, float b) {  // a->lo, b->hi
    uint32_t r;
    asm("cvt.rn.bf16x2.f32 %0, %1, %2;" : "=r"(r) : "f"(b), "f"(a));
    return r;
}
__device__ __forceinline__ float bf16r(float v) {
    return __bfloat162float(__float2bfloat16(v));
}

// ---------------- router + sort (unchanged, validated round 1) ----------------
__global__ void zero_counts_kernel() {
    if (threadIdx.x < E_NUM) d_counts[threadIdx.x] = 0;
}
__global__ void router_kernel(const float* __restrict__ logits) {
    int t = blockIdx.x * blockDim.x + threadIdx.x;
    if (t >= T_TOK) return;
    float l[E_NUM];
#pragma unroll
    for (int e = 0; e < E_NUM; e++) l[e] = logits[t * E_NUM + e];
    int i0 = 0;
#pragma unroll
    for (int e = 1; e < E_NUM; e++) if (l[e] > l[i0]) i0 = e;
    int i1 = (i0 == 0) ? 1 : 0;
#pragma unroll
    for (int e = 0; e < E_NUM; e++) {
        if (e == i0 || e == i1) continue;
        if (l[e] > l[i1]) i1 = e;
    }
    float w0 = 1.f / (1.f + expf(l[i1] - l[i0]));
    d_expert_of_slot[2 * t] = i0; d_expert_of_slot[2 * t + 1] = i1;
    d_w_of_slot[2 * t] = w0;      d_w_of_slot[2 * t + 1] = 1.f - w0;
    atomicAdd(&d_counts[i0], 1);
    atomicAdd(&d_counts[i1], 1);
}
__global__ void setup_kernel() {
    __shared__ int s_off[E_NUM];
    __shared__ int s_cur[E_NUM];
    if (threadIdx.x == 0) {
        int acc = 0, nt = 0;
        for (int e = 0; e < E_NUM; e++) {
            int c = d_counts[e];
            s_off[e] = acc;
            for (int r = 0; r < c; r += BM) {
                d_tile_expert[nt] = e;
                d_tile_row0[nt] = acc + r;
                d_tile_rowend[nt] = acc + c;
                nt++;
            }
            acc += c;
        }
        d_num_tiles = nt;
    }
    if (threadIdx.x < E_NUM) s_cur[threadIdx.x] = 0;
    __syncthreads();
    for (int s = threadIdx.x; s < S_SLOTS; s += blockDim.x) {
        int e = d_expert_of_slot[s];
        int pos = s_off[e] + atomicAdd(&s_cur[e], 1);
        d_perm[pos] = s;
    }
}

// ---------------- prepass: x -> bf16 hi/lo ----------------
__global__ void conv_x_kernel(const float* __restrict__ x) {
    int i = blockIdx.x * blockDim.x + threadIdx.x;
    float4 v = ((const float4*)x)[i];
    uint32_t* oh = (uint32_t*)d_x_h;
    uint32_t* ol = (uint32_t*)d_x_l;
    oh[2 * i]     = packbf(v.x, v.y);
    oh[2 * i + 1] = packbf(v.z, v.w);
    ol[2 * i]     = packbf(v.x - bf16r(v.x), v.y - bf16r(v.y));
    ol[2 * i + 1] = packbf(v.z - bf16r(v.z), v.w - bf16r(v.w));
}

// ---------------- prepass: W[e][K][N] -> Wt[e][N][K] bf16 hi/lo ----------------
template <int WSEL>   // 0 = up_weight, 1 = down_weight
__global__ void conv_wT_kernel(const float* __restrict__ W, int K, int N) {
    __shared__ float tf[32][33];
    __nv_bfloat16* Wh = (WSEL == 0) ? d_upwT_h : d_dnwT_h;
    __nv_bfloat16* Wl = (WSEL == 0) ? d_upwT_l : d_dnwT_l;
    const float* Wm = W + (size_t)blockIdx.z * K * N;
    int n0 = blockIdx.x * 32, k0 = blockIdx.y * 32;
    int tx = threadIdx.x, ty = threadIdx.y;
#pragma unroll
    for (int j = 0; j < 4; j++)
        tf[ty + 8 * j][tx] = Wm[(size_t)(k0 + ty + 8 * j) * N + n0 + tx];
    __syncthreads();
    int pid = tx & 15, half = tx >> 4;
    size_t obase = (size_t)blockIdx.z * N * K;
#pragma unroll
    for (int j = 0; j < 4; j++) {
        int nl = ty + 8 * j;
        float v0 = tf[2 * pid][nl], v1 = tf[2 * pid + 1][nl];
        if (half == 0) {
            uint32_t* dst = (uint32_t*)(Wh + obase + (size_t)(n0 + nl) * K + k0);
            dst[pid] = packbf(v0, v1);
        } else {
            uint32_t* dst = (uint32_t*)(Wl + obase + (size_t)(n0 + nl) * K + k0);
            dst[pid] = packbf(v0 - bf16r(v0), v1 - bf16r(v1));
        }
    }
}

// ---------------- HMMA grouped GEMM ----------------
// smem: 2 stages x 4 planes (Ah,Al,Bh,Bl) x 128 rows x 80B(64 data+16 pad) = 81920 B
#define PLANE_B 10240
#define STAGE_B 40960
#define SMEM_B  81920

template <int G>   // 1 = gate/up + SiLU, 2 = down + weight scatter
__global__ void __launch_bounds__(256, 1) gemm_hmma_kernel() {
    int tile = blockIdx.y;
    if (tile >= d_num_tiles) return;
    const int e = d_tile_expert[tile];
    const int row0 = d_tile_row0[tile];
    const int rowend = d_tile_rowend[tile];
    const int nb = blockIdx.x;

    extern __shared__ char smem[];
    const uint32_t sb = smem_u32(smem);
    const int tid = threadIdx.x, wid = tid >> 5, lane = tid & 31;

    // ---- fill mapping: plane = tid>>6 (Ah,Al,Bh,Bl); rows f and f+64 ----
    const int plane = tid >> 6, f = tid & 63;
    const __nv_bfloat16* p0 = d_x_h;
    const __nv_bfloat16* p1 = d_x_h;
    int z0 = 16, z1 = 16;
    if (plane < 2) {
        const __nv_bfloat16* bp = (G == 1) ? (plane ? d_x_l : d_x_h)
                                           : (plane ? d_hbuf_l : d_hbuf_h);
        int g0 = row0 + f, g1 = row0 + f + 64;
        if (g0 < rowend) p0 = bp + (size_t)(G == 1 ? (d_perm[g0] >> 1) : g0) * 1024; else z0 = 0;
        if (g1 < rowend) p1 = bp + (size_t)(G == 1 ? (d_perm[g1] >> 1) : g1) * 1024; else z1 = 0;
    } else {
        if (G == 1) {
            // interleave gate/up: block col n -> unit nb*64+(n>>1); odd n = up
            const __nv_bfloat16* bp = ((plane == 3) ? d_upwT_l : d_upwT_h)
                                      + (size_t)e * 2 * I_DIM * H_DIM;
            int u0 = nb * 64 + (f >> 1), u1 = u0 + 32;
            p0 = bp + (size_t)((f & 1) ? I_DIM + u0 : u0) * 1024;
            p1 = bp + (size_t)((f & 1) ? I_DIM + u1 : u1) * 1024;
        } else {
            const __nv_bfloat16* bp = ((plane == 3) ? d_dnwT_l : d_dnwT_h)
                                      + (size_t)e * H_DIM * I_DIM;
            p0 = bp + (size_t)(nb * 128 + f) * 1024;
            p1 = bp + (size_t)(nb * 128 + f + 64) * 1024;
        }
    }
    const uint32_t dst0 = sb + plane * PLANE_B + f * 80;
    const uint32_t dst1 = dst0 + 64 * 80;

    // ---- warp tiling: 4 m-warps x 2 n-warps; warp tile 32x64 ----
    const int warp_m = wid >> 1, warp_n = wid & 1;
    const uint32_t a_off = (uint32_t)((warp_m * 32 + (lane & 15)) * 80 + (lane >> 4) * 16);
    const uint32_t b_off = (uint32_t)((warp_n * 64 + ((lane >> 4) & 1) * 8 + (lane & 7)) * 80
                                      + ((lane >> 3) & 1) * 16);

    float acc[2][8][4];
#pragma unroll
    for (int mt = 0; mt < 2; mt++)
#pragma unroll
        for (int nt = 0; nt < 8; nt++)
#pragma unroll
            for (int q = 0; q < 4; q++) acc[mt][nt][q] = 0.f;

    auto fill = [&](int stage, int c) {
        uint32_t s0 = dst0 + stage * STAGE_B;
        uint32_t s1 = dst1 + stage * STAGE_B;
        const char* g0 = (const char*)p0 + c * 64;
        const char* g1 = (const char*)p1 + c * 64;
#pragma unroll
        for (int s = 0; s < 4; s++) CP_ASYNC16(s0 + s * 16, g0 + s * 16, z0);
#pragma unroll
        for (int s = 0; s < 4; s++) CP_ASYNC16(s1 + s * 16, g1 + s * 16, z1);
    };

    fill(0, 0); CP_COMMIT();

    for (int c = 0; c < 32; c++) {
        if (c + 1 < 32) { fill((c + 1) & 1, c + 1); CP_COMMIT(); CP_WAIT1(); }
        else            { CP_WAIT0(); }
        __syncthreads();
        const uint32_t st = sb + (c & 1) * STAGE_B;
#pragma unroll
        for (int kb = 0; kb < 64; kb += 32) {
            uint32_t ah[2][4], al[2][4], bh[4][4], bl[4][4];
#pragma unroll
            for (int mt = 0; mt < 2; mt++) {
                uint32_t aa = st + a_off + mt * 1280 + kb;
                LDSM_X4(ah[mt][0], ah[mt][1], ah[mt][2], ah[mt][3], aa);
                LDSM_X4(al[mt][0], al[mt][1], al[mt][2], al[mt][3], aa + PLANE_B);
            }
#pragma unroll
            for (int bp2 = 0; bp2 < 4; bp2++) {
                uint32_t ba = st + 2 * PLANE_B + b_off + bp2 * 1280 + kb;
                LDSM_X4(bh[bp2][0], bh[bp2][1], bh[bp2][2], bh[bp2][3], ba);
                LDSM_X4(bl[bp2][0], bl[bp2][1], bl[bp2][2], bl[bp2][3], ba + PLANE_B);
            }
#pragma unroll
            for (int mt = 0; mt < 2; mt++)
#pragma unroll
                for (int nt = 0; nt < 8; nt++) {
                    uint32_t h0 = bh[nt >> 1][(nt & 1) * 2], h1 = bh[nt >> 1][(nt & 1) * 2 + 1];
                    uint32_t l0 = bl[nt >> 1][(nt & 1) * 2], l1 = bl[nt >> 1][(nt & 1) * 2 + 1];
                    mma_bf16(acc[mt][nt], ah[mt], h0, h1);
                    mma_bf16(acc[mt][nt], al[mt], h0, h1);
                    mma_bf16(acc[mt][nt], ah[mt], l0, l1);
                }
        }
        __syncthreads();
    }

    // ---- epilogue ----
    if (G == 1) {
#pragma unroll
        for (int mt = 0; mt < 2; mt++) {
            int rA = row0 + warp_m * 32 + mt * 16 + (lane >> 2);
            int rB = rA + 8;
#pragma unroll
            for (int nt = 0; nt < 8; nt++) {
                int col = nb * 64 + warp_n * 32 + nt * 4 + (lane & 3);
                float* d = acc[mt][nt];
                if (rA < rowend) {
                    float g = d[0], u = d[1];
                    float h = g / (1.f + expf(-g)) * u;
                    d_hbuf_h[(size_t)rA * 1024 + col] = __float2bfloat16(h);
                    d_hbuf_l[(size_t)rA * 1024 + col] = __float2bfloat16(h - bf16r(h));
                }
                if (rB < rowend) {
                    float g = d[2], u = d[3];
                    float h = g / (1.f + expf(-g)) * u;
                    d_hbuf_h[(size_t)rB * 1024 + col] = __float2bfloat16(h);
                    d_hbuf_l[(size_t)rB * 1024 + col] = __float2bfloat16(h - bf16r(h));
                }
            }
        }
    } else {
#pragma unroll
        for (int mt = 0; mt < 2; mt++) {
            int rA = row0 + warp_m * 32 + mt * 16 + (lane >> 2);
            int rB = rA + 8;
            if (rA < rowend) {
                int slot = d_perm[rA];
                float w = d_w_of_slot[slot];
                float* po = &d_acc[(size_t)slot * 1024 + nb * 128 + warp_n * 64 + 2 * (lane & 3)];
#pragma unroll
                for (int nt = 0; nt < 8; nt++) {
                    float* d = acc[mt][nt];
                    *(float2*)(po + nt * 8) = make_float2(w * d[0], w * d[1]);
                }
            }
            if (rB < rowend) {
                int slot = d_perm[rB];
                float w = d_w_of_slot[slot];
                float* po = &d_acc[(size_t)slot * 1024 + nb * 128 + warp_n * 64 + 2 * (lane & 3)];
#pragma unroll
                for (int nt = 0; nt < 8; nt++) {
                    float* d = acc[mt][nt];
                    *(float2*)(po + nt * 8) = make_float2(w * d[2], w * d[3]);
                }
            }
        }
    }
}

// ---------------- combine: out[t] = acc[2t] + acc[2t+1] ----------------
__global__ void combine_kernel(float* __restrict__ out) {
    int i = blockIdx.x * blockDim.x + threadIdx.x;
    int t = i / (H_DIM / 4);
    int c = i % (H_DIM / 4);
    const float4* a0 = (const float4*)&d_acc[(size_t)(2 * t) * H_DIM];
    const float4* a1 = (const float4*)&d_acc[(size_t)(2 * t + 1) * H_DIM];
    float4 x0 = a0[c], x1 = a1[c];
    ((float4*)out)[i] = make_float4(x0.x + x1.x, x0.y + x1.y, x0.z + x1.z, x0.w + x1.w);
}

// ---------------- launch ----------------
extern "C" void kernel_launch(void* const* d_in, const int* in_sizes, int n_in,
                              void* d_out, int out_size) {
    (void)in_sizes; (void)n_in; (void)out_size;
    const float* x      = (const float*)d_in[0];
    const float* logits = (const float*)d_in[1];
    const float* up_w   = (const float*)d_in[2];
    const float* down_w = (const float*)d_in[3];
    float* out = (float*)d_out;

    // non-stream attribute set; called every time (no static guards)
    cudaFuncSetAttribute(gemm_hmma_kernel<1>, cudaFuncAttributeMaxDynamicSharedMemorySize, SMEM_B);
    cudaFuncSetAttribute(gemm_hmma_kernel<2>, cudaFuncAttributeMaxDynamicSharedMemorySize, SMEM_B);

    zero_counts_kernel<<<1, 32>>>();
    router_kernel<<<T_TOK / 256, 256>>>(logits);
    setup_kernel<<<1, 256>>>();
    conv_x_kernel<<<T_TOK * H_DIM / 4 / 256, 256>>>(x);
    conv_wT_kernel<0><<<dim3(2 * I_DIM / 32, H_DIM / 32, E_NUM), dim3(32, 8)>>>(up_w, H_DIM, 2 * I_DIM);
    conv_wT_kernel<1><<<dim3(H_DIM / 32, I_DIM / 32, E_NUM), dim3(32, 8)>>>(down_w, I_DIM, H_DIM);
    gemm_hmma_kernel<1><<<dim3(16, MAX_TILES), 256, SMEM_B>>>();
    gemm_hmma_kernel<2><<<dim3(8, MAX_TILES), 256, SMEM_B>>>();
    combine_kernel<<<T_TOK * H_DIM / 4 / 256, 256>>>(out);
}